// round 7
// baseline (speedup 1.0000x reference)
#include <cuda_runtime.h>
#include <math.h>

#define Kc 3
#define Bc 512
#define Dc 1024
#define Hc 512
#define Cc 48
#define Tc 25
#define G4 2048
#define DP1 1025
#define FEATN 6288

// output section offsets (all float32, concatenated in tuple order)
#define O0 0                                  // labels_t   [T,B]
#define O1 (Tc*Bc)                            // probs      [B,T,C]
#define O2 (O1 + Bc*Tc*Cc)                    // curr_action[B,C]
#define O3 (O2 + Bc*Cc)                       // durations  [B,T+1]
#define O4 (O3 + Bc*(Tc+1))                   // att_t      [T,B,D]

// ---------------- scratch (device globals: no allocation allowed) ----------
__device__ float d_Y[Kc*Bc*Cc];
__device__ float d_feat[Bc*FEATN];
__device__ float d_x0[Bc*DP1];
__device__ float d_xp[2*Bc*DP1];
__device__ float d_gx0[Bc*G4];        // x0 @ W_ih^T + bsum
__device__ float d_E[Cc*G4];
__device__ float d_Ep[4*Cc*G4];
__device__ float d_P[Kc*Bc*Hc];
__device__ float d_sdur[Bc*Kc];
__device__ float d_gates[Bc*G4];
__device__ float d_h[2][Bc*Hc];
__device__ float d_c[Bc*Hc];
__device__ int   d_labels[Bc];
__device__ float d_dur[Bc];
__device__ float d_WpT[Cc*Hc];
__device__ float d_wihdur[G4];
__device__ float d_bsum[G4];

// ---------------- packed f32x2 helpers --------------------------------------
typedef unsigned long long ull;

__device__ __forceinline__ void fma2(ull &d, ull a, ull b) {
    asm("fma.rn.f32x2 %0, %1, %2, %0;" : "+l"(d) : "l"(a), "l"(b));
}
__device__ __forceinline__ float2 upk(ull v) {
    float2 r; asm("mov.b64 {%0,%1}, %2;" : "=f"(r.x), "=f"(r.y) : "l"(v)); return r;
}

// ---------------- 64x128 SGEMM, 512 threads, dup-A, f32x2 FMA ---------------
// C[m,n] = sum_k A[m,k]*B'[k,n] (+bias[n]).  KSTEP=16, single-buffered.
// Each thread: 2 rows x 8 cols.  16 warps/SM -> 4 warps/SMSP.
// BT=true : B is [N,K] row-major;  BT=false: B is [K,N] row-major.
template<bool BT>
__global__ void __launch_bounds__(512)
gemm5(const float* __restrict__ A, const float* __restrict__ Bm,
      float* __restrict__ C, int M, int N, int K,
      int lda, int ldb, int ldc, const float* __restrict__ bias,
      long long sA, long long sB, long long sC)
{
    __shared__ __align__(16) float2 As2[16][66];
    __shared__ __align__(16) float  Bs[16][132];

    A  += (size_t)blockIdx.z * sA;
    Bm += (size_t)blockIdx.z * sB;
    C  += (size_t)blockIdx.z * sC;

    const int tid = threadIdx.x;
    const int m0 = blockIdx.y * 64, n0 = blockIdx.x * 128;
    const int tx = tid & 15, ty = tid >> 4;        // compute map: ty 0..31
    const int alk = tid & 15, alm = tid >> 4;      // A / BT-B loader
    const int nn = tid & 127, nk = tid >> 7;       // NN-B loader

    ull acc[2][4];
#pragma unroll
    for (int i = 0; i < 2; i++)
#pragma unroll
        for (int j = 0; j < 4; j++) acc[i][j] = 0ull;

    for (int k0 = 0; k0 < K; k0 += 16) {
        // load A 64x16 (2 elems/thread), dup into float2
#pragma unroll
        for (int i = 0; i < 2; i++) {
            int m = alm + i*32;
            float v = 0.f;
            if (m0 + m < M && k0 + alk < K) v = A[(size_t)(m0+m)*lda + k0 + alk];
            As2[alk][m] = make_float2(v, v);
        }
        if (BT) {
#pragma unroll
            for (int i = 0; i < 4; i++) {
                int n = alm + i*32;
                float v = 0.f;
                if (n0 + n < N && k0 + alk < K) v = Bm[(size_t)(n0+n)*ldb + k0 + alk];
                Bs[alk][n] = v;
            }
        } else {
#pragma unroll
            for (int i = 0; i < 4; i++) {
                int k = nk + i*4;
                float v = 0.f;
                if (k0 + k < K && n0 + nn < N) v = Bm[(size_t)(k0+k)*ldb + n0 + nn];
                Bs[k][nn] = v;
            }
        }
        __syncthreads();
#pragma unroll
        for (int kk = 0; kk < 16; kk++) {
            longlong2 a01 = *(const longlong2*)&As2[kk][ty*2];
            longlong2 b01 = *(const longlong2*)&Bs[kk][tx*4];
            longlong2 b23 = *(const longlong2*)&Bs[kk][64 + tx*4];
            fma2(acc[0][0], (ull)a01.x, (ull)b01.x);
            fma2(acc[0][1], (ull)a01.x, (ull)b01.y);
            fma2(acc[0][2], (ull)a01.x, (ull)b23.x);
            fma2(acc[0][3], (ull)a01.x, (ull)b23.y);
            fma2(acc[1][0], (ull)a01.y, (ull)b01.x);
            fma2(acc[1][1], (ull)a01.y, (ull)b01.y);
            fma2(acc[1][2], (ull)a01.y, (ull)b23.x);
            fma2(acc[1][3], (ull)a01.y, (ull)b23.y);
        }
        __syncthreads();
    }

#pragma unroll
    for (int i = 0; i < 2; i++) {
        int m = m0 + ty*2 + i;
        if (m >= M) continue;
        float* Cr = C + (size_t)m * ldc;
#pragma unroll
        for (int jp = 0; jp < 4; jp++) {
            float2 v = upk(acc[i][jp]);
            int nb = n0 + ((jp >= 2) ? 64 : 0) + tx*4 + (jp & 1)*2;
            if (nb < N)     Cr[nb]     = v.x + (bias ? bias[nb]     : 0.f);
            if (nb + 1 < N) Cr[nb + 1] = v.y + (bias ? bias[nb + 1] : 0.f);
        }
    }
}

// ---------------- split-K reduce --------------------------------------------
__global__ void reduce_add(const float* __restrict__ part, float* __restrict__ outp,
                           int n, int nparts, long long stride,
                           const float* __restrict__ bias, int ldc)
{
    int i = blockIdx.x * blockDim.x + threadIdx.x;
    if (i >= n) return;
    float s = 0.f;
    for (int z = 0; z < nparts; z++) s += part[(size_t)z*stride + i];
    if (bias) s += bias[i % ldc];
    outp[i] = s;
}

// ---------------- init ------------------------------------------------------
__global__ void init_kernel(const float* __restrict__ W_ih,
                            const float* __restrict__ b_ih,
                            const float* __restrict__ b_hh,
                            const float* __restrict__ Wp)
{
    for (int i = blockIdx.x*blockDim.x + threadIdx.x; i < Bc*Hc;
         i += gridDim.x*blockDim.x) {
        d_h[0][i] = 0.f; d_c[i] = 0.f;
        if (i < Cc*Hc) {
            int c = i >> 9, h = i & 511;
            d_WpT[i] = Wp[h*Cc + c];
        }
        if (i < G4) {
            d_wihdur[i] = W_ih[(size_t)i*DP1 + Dc];
            d_bsum[i]   = b_ih[i] + b_hh[i];
        }
    }
}

// ---------------- fused classifier: logits + softmax ------------------------
__global__ void __launch_bounds__(256)
cls_kernel(const float* __restrict__ S, const float* __restrict__ R,
           const float* __restrict__ W, const float* __restrict__ bcls)
{
    __shared__ __align__(16) float As[32][20];
    __shared__ __align__(16) float Bs[48][20];
    const int k  = blockIdx.y;
    const int b0 = blockIdx.x * 32;
    const int tid = threadIdx.x;
    const int rr = tid >> 3, cs = tid & 7;
    float acc[6] = {};

    for (int ph = 0; ph < 2; ph++) {
        const float* Ap = (ph ? R : S) + ((size_t)k*Bc + b0)*Dc;
        const float* Wb = W + ((size_t)k*2*Dc + (size_t)ph*Dc)*Cc;
        for (int k0 = 0; k0 < Dc; k0 += 16) {
            {   int lk = tid & 15, lr = tid >> 4;
                As[lr][lk]      = Ap[(size_t)lr*Dc + k0 + lk];
                As[lr + 16][lk] = Ap[(size_t)(lr + 16)*Dc + k0 + lk];
            }
#pragma unroll
            for (int j = 0; j < 3; j++) {
                int idx = tid + j*256;
                int c = idx >> 4, kk = idx & 15;
                Bs[c][kk] = Wb[(size_t)(k0 + kk)*Cc + c];
            }
            __syncthreads();
#pragma unroll
            for (int kq = 0; kq < 4; kq++) {
                float4 a = *reinterpret_cast<const float4*>(&As[rr][kq*4]);
#pragma unroll
                for (int j = 0; j < 6; j++) {
                    float4 b = *reinterpret_cast<const float4*>(&Bs[cs + 8*j][kq*4]);
                    acc[j] = fmaf(a.x, b.x, acc[j]);
                    acc[j] = fmaf(a.y, b.y, acc[j]);
                    acc[j] = fmaf(a.z, b.z, acc[j]);
                    acc[j] = fmaf(a.w, b.w, acc[j]);
                }
            }
            __syncthreads();
        }
    }
    float mx = -3.4e38f;
#pragma unroll
    for (int j = 0; j < 6; j++) {
        acc[j] += bcls[k*Cc + cs + 8*j];
        mx = fmaxf(mx, acc[j]);
    }
    for (int o = 4; o; o >>= 1) mx = fmaxf(mx, __shfl_xor_sync(0xffffffffu, mx, o));
    float sum = 0.f;
#pragma unroll
    for (int j = 0; j < 6; j++) { acc[j] = expf(acc[j] - mx); sum += acc[j]; }
    for (int o = 4; o; o >>= 1) sum += __shfl_xor_sync(0xffffffffu, sum, o);
    float inv = 1.f / sum;
    float* Yr = d_Y + ((size_t)k*Bc + b0 + rr)*Cc;
#pragma unroll
    for (int j = 0; j < 6; j++) Yr[cs + 8*j] = acc[j] * inv;
}

// feat assembly + curr_action + curr_dur + sdur ; one block per b
__global__ void prep_kernel(const float* __restrict__ S, const float* __restrict__ R,
                            const float* __restrict__ dur_W, const float* __restrict__ dur_b,
                            const float* __restrict__ Wdur, float* __restrict__ out)
{
    __shared__ float red[256];
    const int b = blockIdx.x, tid = threadIdx.x;
    float* fr = d_feat + (size_t)b * FEATN;
    for (int i = tid; i < Kc*Cc; i += 256) {
        int k = i / Cc, c = i - k*Cc;
        fr[i] = d_Y[((size_t)k*Bc + b)*Cc + c];
    }
    for (int i = tid; i < Kc*Dc; i += 256) {
        int k = i >> 10, d = i & 1023;
        fr[Kc*Cc + i]         = S[((size_t)k*Bc + b)*Dc + d];
        fr[Kc*Cc + Kc*Dc + i] = R[((size_t)k*Bc + b)*Dc + d];
    }
    for (int i = tid; i < Cc; i += 256)
        out[O2 + (size_t)b*Cc + i] = d_Y[(size_t)b*Cc + i]
                                   + d_Y[((size_t)Bc + b)*Cc + i]
                                   + d_Y[((size_t)2*Bc + b)*Cc + i];
    float pd = 0.f;
    for (int i = tid; i < Kc*Dc; i += 256) {
        int k = i >> 10, d = i & 1023;
        pd += R[((size_t)k*Bc + b)*Dc + d] * dur_W[i];
    }
    red[tid] = pd; __syncthreads();
    for (int s = 128; s > 0; s >>= 1) { if (tid < s) red[tid] += red[tid + s]; __syncthreads(); }
    if (tid == 0) out[O3 + (size_t)b*(Tc+1)] = red[0] + dur_b[0];
    __syncthreads();
    for (int k = 0; k < Kc; k++) {
        float ps = 0.f;
        for (int d = tid; d < Dc; d += 256)
            ps += S[((size_t)k*Bc + b)*Dc + d] * Wdur[d];
        red[tid] = ps; __syncthreads();
        for (int s = 128; s > 0; s >>= 1) { if (tid < s) red[tid] += red[tid + s]; __syncthreads(); }
        if (tid == 0) d_sdur[b*Kc + k] = red[0];
        __syncthreads();
    }
}

// fused per-step kernel: LSTM elementwise + logits/probs/argmax + attention +
// dur ; one block per b, 512 threads (16 warps). bsum already folded in GEMMs.
__global__ void __launch_bounds__(512)
step_kernel(const float* __restrict__ S, const float* __restrict__ bp,
            const float* __restrict__ Wdur, const float* __restrict__ bdur,
            float* __restrict__ out, int t, int sel)
{
    __shared__ float sh[Hc];
    __shared__ float slog[Cc];
    __shared__ float sscore[3];
    __shared__ float saw[3];
    __shared__ float sred[16];
    const int b  = blockIdx.x;
    const int th = threadIdx.x;
    const int wid = th >> 5, lane = th & 31;
    const float* h_in = d_h[sel];
    float* h_out = d_h[sel ^ 1];

    float g[4];
    if (t == 0) {
#pragma unroll
        for (int j = 0; j < 4; j++) g[j] = d_gx0[(size_t)b*G4 + j*Hc + th];
    } else {
        int lab = d_labels[b];
        float dp = d_dur[b];
#pragma unroll
        for (int j = 0; j < 4; j++) {
            int gi = j*Hc + th;
            g[j] = d_gates[(size_t)b*G4 + gi] + d_E[(size_t)lab*G4 + gi]
                 + dp * d_wihdur[gi];
        }
    }
    float ig = 1.f / (1.f + expf(-g[0]));
    float fg = 1.f / (1.f + expf(-g[1]));
    float gg = tanhf(g[2]);
    float og = 1.f / (1.f + expf(-g[3]));
    int idx = b*Hc + th;
    float cn = fg * d_c[idx] + ig * gg;
    d_c[idx] = cn;
    float hn = og * tanhf(cn);
    h_out[idx] = hn;
    sh[th] = hn;
    float hp = h_in[idx] * Wdur[Dc + th];
    for (int o = 16; o; o >>= 1) hp += __shfl_xor_sync(0xffffffffu, hp, o);
    if (lane == 0) sred[wid] = hp;
    __syncthreads();

    for (int cc = wid; cc < Cc; cc += 16) {
        float s = 0.f;
        const float* wr = d_WpT + (size_t)cc*Hc;
        for (int j = lane; j < Hc; j += 32) s += sh[j] * wr[j];
        for (int o = 16; o; o >>= 1) s += __shfl_xor_sync(0xffffffffu, s, o);
        if (lane == 0) slog[cc] = s + bp[cc];
    }
    if (wid < 3) {
        float s = 0.f;
        const float* Pr = d_P + ((size_t)wid*Bc + b)*Hc;
        for (int j = lane; j < Hc; j += 32) s += sh[j] * Pr[j];
        for (int o = 16; o; o >>= 1) s += __shfl_xor_sync(0xffffffffu, s, o);
        if (lane == 0) sscore[wid] = s * 0.03125f;  // 1/sqrt(1024)
    }
    __syncthreads();

    if (wid == 0) {
        float v1 = slog[lane];
        float v2 = (lane < Cc - 32) ? slog[32 + lane] : -3.4e38f;
        float m = fmaxf(v1, v2);
        for (int o = 16; o; o >>= 1) m = fmaxf(m, __shfl_xor_sync(0xffffffffu, m, o));
        float e1 = expf(v1 - m);
        float e2 = (lane < Cc - 32) ? expf(v2 - m) : 0.f;
        float s = e1 + e2;
        for (int o = 16; o; o >>= 1) s += __shfl_xor_sync(0xffffffffu, s, o);
        float inv = 1.f / s;
        size_t pb = O1 + ((size_t)b*Tc + t)*Cc;
        out[pb + lane] = e1 * inv;
        if (lane < Cc - 32) out[pb + 32 + lane] = e2 * inv;
        float bv; int bi;
        if (lane < Cc - 32 && v2 > v1) { bv = v2; bi = 32 + lane; }
        else                           { bv = v1; bi = lane; }
        for (int o = 16; o; o >>= 1) {
            float ov = __shfl_xor_sync(0xffffffffu, bv, o);
            int   oi = __shfl_xor_sync(0xffffffffu, bi, o);
            if (ov > bv || (ov == bv && oi < bi)) { bv = ov; bi = oi; }
        }
        float hv = (lane < 16) ? sred[lane] : 0.f;
        for (int o = 8; o; o >>= 1) hv += __shfl_xor_sync(0xffffffffu, hv, o);
        if (lane == 0) {
            out[O0 + (size_t)t*Bc + b] = (float)bi;
            d_labels[b] = bi;
            float s0 = sscore[0], s1 = sscore[1], s2 = sscore[2];
            float sm = fmaxf(s0, fmaxf(s1, s2));
            float a0 = expf(s0 - sm), a1 = expf(s1 - sm), a2 = expf(s2 - sm);
            float z = 1.f / (a0 + a1 + a2);
            a0 *= z; a1 *= z; a2 *= z;
            saw[0] = a0; saw[1] = a1; saw[2] = a2;
            float dur = a0*d_sdur[b*Kc] + a1*d_sdur[b*Kc+1] + a2*d_sdur[b*Kc+2]
                      + hv + bdur[0];
            out[O3 + (size_t)b*(Tc+1) + t + 1] = dur;
            d_dur[b] = dur;
        }
    }
    __syncthreads();

    float a0 = saw[0], a1 = saw[1], a2 = saw[2];
    size_t ab = O4 + ((size_t)t*Bc + b)*Dc;
    const float* S0 = S + (size_t)b*Dc;
    const float* S1 = S + ((size_t)Bc + b)*Dc;
    const float* S2 = S + ((size_t)2*Bc + b)*Dc;
    for (int d = th; d < Dc; d += 512)
        out[ab + d] = a0*S0[d] + a1*S1[d] + a2*S2[d];
}

// ---------------- host ------------------------------------------------------
extern "C" void kernel_launch(void* const* d_in, const int* in_sizes, int n_in,
                              void* d_out, int out_size)
{
    const float* S     = (const float*)d_in[0];
    const float* R     = (const float*)d_in[1];
    const float* cls_W = (const float*)d_in[2];
    const float* cls_b = (const float*)d_in[3];
    const float* dur_W = (const float*)d_in[4];
    const float* dur_b = (const float*)d_in[5];
    const float* lin_W = (const float*)d_in[6];
    const float* lin_b = (const float*)d_in[7];
    const float* W_ih  = (const float*)d_in[8];
    const float* W_hh  = (const float*)d_in[9];
    const float* b_ih  = (const float*)d_in[10];
    const float* b_hh  = (const float*)d_in[11];
    const float* Wp    = (const float*)d_in[12];
    const float* bp    = (const float*)d_in[13];
    const float* Wdur  = (const float*)d_in[14];
    const float* bdur  = (const float*)d_in[15];
    const float* embed = (const float*)d_in[16];
    const float* Wattn = (const float*)d_in[17];
    float* out = (float*)d_out;

    float *pfeat, *px0, *pxp, *pgx0, *pE, *pEp, *pP, *pgates, *ph, *pbsum;
    cudaGetSymbolAddress((void**)&pfeat,  d_feat);
    cudaGetSymbolAddress((void**)&px0,    d_x0);
    cudaGetSymbolAddress((void**)&pxp,    d_xp);
    cudaGetSymbolAddress((void**)&pgx0,   d_gx0);
    cudaGetSymbolAddress((void**)&pE,     d_E);
    cudaGetSymbolAddress((void**)&pEp,    d_Ep);
    cudaGetSymbolAddress((void**)&pP,     d_P);
    cudaGetSymbolAddress((void**)&pgates, d_gates);
    cudaGetSymbolAddress((void**)&ph,     d_h);
    cudaGetSymbolAddress((void**)&pbsum,  d_bsum);

    init_kernel<<<256, 512>>>(W_ih, b_ih, b_hh, Wp);

    cls_kernel<<<dim3(Bc/32, Kc), 256>>>(S, R, cls_W, cls_b);
    prep_kernel<<<Bc, 256>>>(S, R, dur_W, dur_b, Wdur, out);

    // x0 = feat @ lin_W + lin_b   [512 x 1025, K=6288]  split-K 2 (grid 144)
    gemm5<false><<<dim3(9, 8, 2), 512>>>(
        pfeat, lin_W, pxp, Bc, DP1, FEATN/2, FEATN, DP1, DP1, nullptr,
        (long long)(FEATN/2), (long long)(FEATN/2)*DP1, (long long)Bc*DP1);
    reduce_add<<<(Bc*DP1 + 255)/256, 256>>>(pxp, px0, Bc*DP1, 2,
                                            (long long)Bc*DP1, lin_b, DP1);
    // gx0 = x0 @ W_ih^T + bsum   [512 x 2048, K=1025]  (grid 128)
    gemm5<true><<<dim3(16, 8), 512>>>(
        px0, W_ih, pgx0, Bc, G4, DP1, DP1, DP1, G4, pbsum, 0, 0, 0);
    // E = embed @ W_ih[:, :D]^T  [48 x 2048, K=1024]  split-K 4 (grid 64)
    gemm5<true><<<dim3(16, 1, 4), 512>>>(
        embed, W_ih, pEp, Cc, G4, Dc/4, Dc, DP1, G4, nullptr,
        (long long)(Dc/4), (long long)(Dc/4), (long long)Cc*G4);
    reduce_add<<<(Cc*G4 + 255)/256, 256>>>(pEp, pE, Cc*G4, 4,
                                           (long long)Cc*G4, nullptr, G4);
    // P_k = S_k @ Wattn^T        [512 x 512, K=1024]  batched x3 (grid 96)
    gemm5<true><<<dim3(4, 8, 3), 512>>>(
        S, Wattn, pP, Bc, Hc, Dc, Dc, Dc, Hc, nullptr,
        (long long)Bc*Dc, 0, (long long)Bc*Hc);

    int sel = 0;
    for (int t = 0; t < Tc; t++) {
        if (t > 0)
            gemm5<true><<<dim3(16, 8), 512>>>(
                ph + (size_t)sel*Bc*Hc, W_hh, pgates,
                Bc, G4, Hc, Hc, Hc, G4, pbsum, 0, 0, 0);
        step_kernel<<<Bc, 512>>>(S, bp, Wdur, bdur, out, t, sel);
        sel ^= 1;
    }
}

// round 8
// speedup vs baseline: 1.0443x; 1.0443x over previous
#include <cuda_runtime.h>
#include <math.h>

#define Kc 3
#define Bc 512
#define Dc 1024
#define Hc 512
#define Cc 48
#define Tc 25
#define G4 2048
#define DP1 1025
#define FEATN 6288

// output section offsets (all float32, concatenated in tuple order)
#define O0 0                                  // labels_t   [T,B]
#define O1 (Tc*Bc)                            // probs      [B,T,C]
#define O2 (O1 + Bc*Tc*Cc)                    // curr_action[B,C]
#define O3 (O2 + Bc*Cc)                       // durations  [B,T+1]
#define O4 (O3 + Bc*(Tc+1))                   // att_t      [T,B,D]

// ---------------- scratch (device globals: no allocation allowed) ----------
__device__ float d_Y[Kc*Bc*Cc];
__device__ float d_feat[Bc*FEATN];
__device__ float d_x0[Bc*DP1];
__device__ float d_xp[2*Bc*DP1];
__device__ float d_gx0[Bc*G4];        // x0 @ W_ih^T + bsum
__device__ float d_E[Cc*G4];
__device__ float d_Ep[4*Cc*G4];
__device__ float d_P[Kc*Bc*Hc];
__device__ float d_sdur[Bc*Kc];
__device__ float d_gates[Bc*G4];
__device__ float d_h[2][Bc*Hc];
__device__ float d_c[Bc*Hc];
__device__ int   d_labels[Bc];
__device__ float d_dur[Bc];
__device__ float d_WpT[Cc*Hc];
__device__ float d_wihdur[G4];
__device__ float d_bsum[G4];

// ---------------- packed f32x2 helpers --------------------------------------
typedef unsigned long long ull;

__device__ __forceinline__ ull pk(float lo, float hi) {
    ull r; asm("mov.b64 %0, {%1,%2};" : "=l"(r) : "f"(lo), "f"(hi)); return r;
}
__device__ __forceinline__ void fma2(ull &d, ull a, ull b) {
    asm("fma.rn.f32x2 %0, %1, %2, %0;" : "+l"(d) : "l"(a), "l"(b));
}
__device__ __forceinline__ float2 upk(ull v) {
    float2 r; asm("mov.b64 {%0,%1}, %2;" : "=f"(r.x), "=f"(r.y) : "l"(v)); return r;
}

// ---------------- gemm6: 64x128 tile, 256 thr, 8x4 microtile packed-M -------
// C[m,n] = sum_k A[m,k]*B'[k,n] (+bias[n]).  KSTEP=16, single-buffered.
// Accumulators are f32x2 over ROW pairs: A loads are naturally-packed float2
// (zero movs), only 4 B scalars/kk get dup movs (alu pipe).
// Per warp*kk: A = 32B broadcast, B = 1 LDS.128 -> ~6 smem-wf vs 16 FFMA2.
// BT=true : B is [N,K] row-major;  BT=false: B is [K,N] row-major.
template<bool BT>
__global__ void __launch_bounds__(256)
gemm6(const float* __restrict__ A, const float* __restrict__ Bm,
      float* __restrict__ C, int M, int N, int K,
      int lda, int ldb, int ldc, const float* __restrict__ bias,
      long long sA, long long sB, long long sC)
{
    __shared__ __align__(16) float As[16][64];
    __shared__ __align__(16) float Bs[16][128];

    A  += (size_t)blockIdx.z * sA;
    Bm += (size_t)blockIdx.z * sB;
    C  += (size_t)blockIdx.z * sC;

    const int tid = threadIdx.x;
    const int m0 = blockIdx.y * 64, n0 = blockIdx.x * 128;
    const int tx = tid & 31, ty = tid >> 5;       // compute: cols 4tx.., rows 8ty..
    const int ar = tid >> 2, akq = tid & 3;       // A loader: row, k-quad
    const int bn = tid >> 1, bkh = tid & 1;       // BT-B loader: n, k-half
    const int cnb = (tid & 31) * 4, ckk = tid >> 5; // NN-B loader

    ull acc[4][4];
#pragma unroll
    for (int i = 0; i < 4; i++)
#pragma unroll
        for (int j = 0; j < 4; j++) acc[i][j] = 0ull;

    for (int k0 = 0; k0 < K; k0 += 16) {
        // ---- load A 64x16 -> As[kk][m] ----
#pragma unroll
        for (int j = 0; j < 4; j++) {
            int k = k0 + 4*akq + j;
            float v = 0.f;
            if (m0 + ar < M && k < K) v = A[(size_t)(m0+ar)*lda + k];
            As[4*akq + j][ar] = v;
        }
        // ---- load B 16x128 -> Bs[kk][n] ----
        if (BT) {
#pragma unroll
            for (int j = 0; j < 8; j++) {
                int k = k0 + 8*bkh + j;
                float v = 0.f;
                if (n0 + bn < N && k < K) v = Bm[(size_t)(n0+bn)*ldb + k];
                Bs[8*bkh + j][bn] = v;
            }
        } else {
#pragma unroll
            for (int i = 0; i < 2; i++)
#pragma unroll
                for (int j = 0; j < 4; j++) {
                    int k = k0 + ckk + i*8;
                    int n = n0 + cnb + j;
                    float v = 0.f;
                    if (k < K && n < N) v = Bm[(size_t)k*ldb + n];
                    Bs[ckk + i*8][cnb + j] = v;
                }
        }
        __syncthreads();
#pragma unroll
        for (int kk = 0; kk < 16; kk++) {
            float4 a0 = *reinterpret_cast<const float4*>(&As[kk][8*ty]);
            float4 a1 = *reinterpret_cast<const float4*>(&As[kk][8*ty + 4]);
            float4 b  = *reinterpret_cast<const float4*>(&Bs[kk][4*tx]);
            ull Ap0 = reinterpret_cast<const ull*>(&a0)[0];  // rows 8ty,8ty+1
            ull Ap1 = reinterpret_cast<const ull*>(&a0)[1];  // rows +2,+3
            ull Ap2 = reinterpret_cast<const ull*>(&a1)[0];  // rows +4,+5
            ull Ap3 = reinterpret_cast<const ull*>(&a1)[1];  // rows +6,+7
            ull B0 = pk(b.x, b.x), B1 = pk(b.y, b.y);
            ull B2 = pk(b.z, b.z), B3 = pk(b.w, b.w);
            fma2(acc[0][0], Ap0, B0); fma2(acc[0][1], Ap0, B1);
            fma2(acc[0][2], Ap0, B2); fma2(acc[0][3], Ap0, B3);
            fma2(acc[1][0], Ap1, B0); fma2(acc[1][1], Ap1, B1);
            fma2(acc[1][2], Ap1, B2); fma2(acc[1][3], Ap1, B3);
            fma2(acc[2][0], Ap2, B0); fma2(acc[2][1], Ap2, B1);
            fma2(acc[2][2], Ap2, B2); fma2(acc[2][3], Ap2, B3);
            fma2(acc[3][0], Ap3, B0); fma2(acc[3][1], Ap3, B1);
            fma2(acc[3][2], Ap3, B2); fma2(acc[3][3], Ap3, B3);
        }
        __syncthreads();
    }

    // epilogue: rows m0+8ty+2i (+1), cols n0+4tx+j
#pragma unroll
    for (int i = 0; i < 4; i++) {
        int mA = m0 + 8*ty + 2*i;
        int mB = mA + 1;
#pragma unroll
        for (int j = 0; j < 4; j++) {
            int n = n0 + 4*tx + j;
            if (n >= N) continue;
            float2 v = upk(acc[i][j]);
            float bb = bias ? bias[n] : 0.f;
            if (mA < M) C[(size_t)mA*ldc + n] = v.x + bb;
            if (mB < M) C[(size_t)mB*ldc + n] = v.y + bb;
        }
    }
}

// ---------------- split-K reduce --------------------------------------------
__global__ void reduce_add(const float* __restrict__ part, float* __restrict__ outp,
                           int n, int nparts, long long stride,
                           const float* __restrict__ bias, int ldc)
{
    int i = blockIdx.x * blockDim.x + threadIdx.x;
    if (i >= n) return;
    float s = 0.f;
    for (int z = 0; z < nparts; z++) s += part[(size_t)z*stride + i];
    if (bias) s += bias[i % ldc];
    outp[i] = s;
}

// ---------------- init ------------------------------------------------------
__global__ void init_kernel(const float* __restrict__ W_ih,
                            const float* __restrict__ b_ih,
                            const float* __restrict__ b_hh,
                            const float* __restrict__ Wp)
{
    for (int i = blockIdx.x*blockDim.x + threadIdx.x; i < Bc*Hc;
         i += gridDim.x*blockDim.x) {
        d_h[0][i] = 0.f; d_c[i] = 0.f;
        if (i < Cc*Hc) {
            int c = i >> 9, h = i & 511;
            d_WpT[i] = Wp[h*Cc + c];
        }
        if (i < G4) {
            d_wihdur[i] = W_ih[(size_t)i*DP1 + Dc];
            d_bsum[i]   = b_ih[i] + b_hh[i];
        }
    }
}

// ---------------- fused classifier: logits + softmax ------------------------
__global__ void __launch_bounds__(256)
cls_kernel(const float* __restrict__ S, const float* __restrict__ R,
           const float* __restrict__ W, const float* __restrict__ bcls)
{
    __shared__ __align__(16) float As[32][20];
    __shared__ __align__(16) float Bs[48][20];
    const int k  = blockIdx.y;
    const int b0 = blockIdx.x * 32;
    const int tid = threadIdx.x;
    const int rr = tid >> 3, cs = tid & 7;
    float acc[6] = {};

    for (int ph = 0; ph < 2; ph++) {
        const float* Ap = (ph ? R : S) + ((size_t)k*Bc + b0)*Dc;
        const float* Wb = W + ((size_t)k*2*Dc + (size_t)ph*Dc)*Cc;
        for (int k0 = 0; k0 < Dc; k0 += 16) {
            {   int lk = tid & 15, lr = tid >> 4;
                As[lr][lk]      = Ap[(size_t)lr*Dc + k0 + lk];
                As[lr + 16][lk] = Ap[(size_t)(lr + 16)*Dc + k0 + lk];
            }
#pragma unroll
            for (int j = 0; j < 3; j++) {
                int idx = tid + j*256;
                int c = idx >> 4, kk = idx & 15;
                Bs[c][kk] = Wb[(size_t)(k0 + kk)*Cc + c];
            }
            __syncthreads();
#pragma unroll
            for (int kq = 0; kq < 4; kq++) {
                float4 a = *reinterpret_cast<const float4*>(&As[rr][kq*4]);
#pragma unroll
                for (int j = 0; j < 6; j++) {
                    float4 b = *reinterpret_cast<const float4*>(&Bs[cs + 8*j][kq*4]);
                    acc[j] = fmaf(a.x, b.x, acc[j]);
                    acc[j] = fmaf(a.y, b.y, acc[j]);
                    acc[j] = fmaf(a.z, b.z, acc[j]);
                    acc[j] = fmaf(a.w, b.w, acc[j]);
                }
            }
            __syncthreads();
        }
    }
    float mx = -3.4e38f;
#pragma unroll
    for (int j = 0; j < 6; j++) {
        acc[j] += bcls[k*Cc + cs + 8*j];
        mx = fmaxf(mx, acc[j]);
    }
    for (int o = 4; o; o >>= 1) mx = fmaxf(mx, __shfl_xor_sync(0xffffffffu, mx, o));
    float sum = 0.f;
#pragma unroll
    for (int j = 0; j < 6; j++) { acc[j] = expf(acc[j] - mx); sum += acc[j]; }
    for (int o = 4; o; o >>= 1) sum += __shfl_xor_sync(0xffffffffu, sum, o);
    float inv = 1.f / sum;
    float* Yr = d_Y + ((size_t)k*Bc + b0 + rr)*Cc;
#pragma unroll
    for (int j = 0; j < 6; j++) Yr[cs + 8*j] = acc[j] * inv;
}

// feat assembly + curr_action + curr_dur + sdur ; one block per b
__global__ void prep_kernel(const float* __restrict__ S, const float* __restrict__ R,
                            const float* __restrict__ dur_W, const float* __restrict__ dur_b,
                            const float* __restrict__ Wdur, float* __restrict__ out)
{
    __shared__ float red[256];
    const int b = blockIdx.x, tid = threadIdx.x;
    float* fr = d_feat + (size_t)b * FEATN;
    for (int i = tid; i < Kc*Cc; i += 256) {
        int k = i / Cc, c = i - k*Cc;
        fr[i] = d_Y[((size_t)k*Bc + b)*Cc + c];
    }
    for (int i = tid; i < Kc*Dc; i += 256) {
        int k = i >> 10, d = i & 1023;
        fr[Kc*Cc + i]         = S[((size_t)k*Bc + b)*Dc + d];
        fr[Kc*Cc + Kc*Dc + i] = R[((size_t)k*Bc + b)*Dc + d];
    }
    for (int i = tid; i < Cc; i += 256)
        out[O2 + (size_t)b*Cc + i] = d_Y[(size_t)b*Cc + i]
                                   + d_Y[((size_t)Bc + b)*Cc + i]
                                   + d_Y[((size_t)2*Bc + b)*Cc + i];
    float pd = 0.f;
    for (int i = tid; i < Kc*Dc; i += 256) {
        int k = i >> 10, d = i & 1023;
        pd += R[((size_t)k*Bc + b)*Dc + d] * dur_W[i];
    }
    red[tid] = pd; __syncthreads();
    for (int s = 128; s > 0; s >>= 1) { if (tid < s) red[tid] += red[tid + s]; __syncthreads(); }
    if (tid == 0) out[O3 + (size_t)b*(Tc+1)] = red[0] + dur_b[0];
    __syncthreads();
    for (int k = 0; k < Kc; k++) {
        float ps = 0.f;
        for (int d = tid; d < Dc; d += 256)
            ps += S[((size_t)k*Bc + b)*Dc + d] * Wdur[d];
        red[tid] = ps; __syncthreads();
        for (int s = 128; s > 0; s >>= 1) { if (tid < s) red[tid] += red[tid + s]; __syncthreads(); }
        if (tid == 0) d_sdur[b*Kc + k] = red[0];
        __syncthreads();
    }
}

// fused per-step kernel: LSTM elementwise + logits/probs/argmax + attention +
// dur ; one block per b, 512 threads (16 warps). bsum already folded in GEMMs.
__global__ void __launch_bounds__(512)
step_kernel(const float* __restrict__ S, const float* __restrict__ bp,
            const float* __restrict__ Wdur, const float* __restrict__ bdur,
            float* __restrict__ out, int t, int sel)
{
    __shared__ float sh[Hc];
    __shared__ float slog[Cc];
    __shared__ float sscore[3];
    __shared__ float saw[3];
    __shared__ float sred[16];
    const int b  = blockIdx.x;
    const int th = threadIdx.x;
    const int wid = th >> 5, lane = th & 31;
    const float* h_in = d_h[sel];
    float* h_out = d_h[sel ^ 1];

    float g[4];
    if (t == 0) {
#pragma unroll
        for (int j = 0; j < 4; j++) g[j] = d_gx0[(size_t)b*G4 + j*Hc + th];
    } else {
        int lab = d_labels[b];
        float dp = d_dur[b];
#pragma unroll
        for (int j = 0; j < 4; j++) {
            int gi = j*Hc + th;
            g[j] = d_gates[(size_t)b*G4 + gi] + d_E[(size_t)lab*G4 + gi]
                 + dp * d_wihdur[gi];
        }
    }
    float ig = 1.f / (1.f + expf(-g[0]));
    float fg = 1.f / (1.f + expf(-g[1]));
    float gg = tanhf(g[2]);
    float og = 1.f / (1.f + expf(-g[3]));
    int idx = b*Hc + th;
    float cn = fg * d_c[idx] + ig * gg;
    d_c[idx] = cn;
    float hn = og * tanhf(cn);
    h_out[idx] = hn;
    sh[th] = hn;
    float hp = h_in[idx] * Wdur[Dc + th];
    for (int o = 16; o; o >>= 1) hp += __shfl_xor_sync(0xffffffffu, hp, o);
    if (lane == 0) sred[wid] = hp;
    __syncthreads();

    for (int cc = wid; cc < Cc; cc += 16) {
        float s = 0.f;
        const float* wr = d_WpT + (size_t)cc*Hc;
        for (int j = lane; j < Hc; j += 32) s += sh[j] * wr[j];
        for (int o = 16; o; o >>= 1) s += __shfl_xor_sync(0xffffffffu, s, o);
        if (lane == 0) slog[cc] = s + bp[cc];
    }
    if (wid < 3) {
        float s = 0.f;
        const float* Pr = d_P + ((size_t)wid*Bc + b)*Hc;
        for (int j = lane; j < Hc; j += 32) s += sh[j] * Pr[j];
        for (int o = 16; o; o >>= 1) s += __shfl_xor_sync(0xffffffffu, s, o);
        if (lane == 0) sscore[wid] = s * 0.03125f;  // 1/sqrt(1024)
    }
    __syncthreads();

    if (wid == 0) {
        float v1 = slog[lane];
        float v2 = (lane < Cc - 32) ? slog[32 + lane] : -3.4e38f;
        float m = fmaxf(v1, v2);
        for (int o = 16; o; o >>= 1) m = fmaxf(m, __shfl_xor_sync(0xffffffffu, m, o));
        float e1 = expf(v1 - m);
        float e2 = (lane < Cc - 32) ? expf(v2 - m) : 0.f;
        float s = e1 + e2;
        for (int o = 16; o; o >>= 1) s += __shfl_xor_sync(0xffffffffu, s, o);
        float inv = 1.f / s;
        size_t pb = O1 + ((size_t)b*Tc + t)*Cc;
        out[pb + lane] = e1 * inv;
        if (lane < Cc - 32) out[pb + 32 + lane] = e2 * inv;
        float bv; int bi;
        if (lane < Cc - 32 && v2 > v1) { bv = v2; bi = 32 + lane; }
        else                           { bv = v1; bi = lane; }
        for (int o = 16; o; o >>= 1) {
            float ov = __shfl_xor_sync(0xffffffffu, bv, o);
            int   oi = __shfl_xor_sync(0xffffffffu, bi, o);
            if (ov > bv || (ov == bv && oi < bi)) { bv = ov; bi = oi; }
        }
        float hv = (lane < 16) ? sred[lane] : 0.f;
        for (int o = 8; o; o >>= 1) hv += __shfl_xor_sync(0xffffffffu, hv, o);
        if (lane == 0) {
            out[O0 + (size_t)t*Bc + b] = (float)bi;
            d_labels[b] = bi;
            float s0 = sscore[0], s1 = sscore[1], s2 = sscore[2];
            float sm = fmaxf(s0, fmaxf(s1, s2));
            float a0 = expf(s0 - sm), a1 = expf(s1 - sm), a2 = expf(s2 - sm);
            float z = 1.f / (a0 + a1 + a2);
            a0 *= z; a1 *= z; a2 *= z;
            saw[0] = a0; saw[1] = a1; saw[2] = a2;
            float dur = a0*d_sdur[b*Kc] + a1*d_sdur[b*Kc+1] + a2*d_sdur[b*Kc+2]
                      + hv + bdur[0];
            out[O3 + (size_t)b*(Tc+1) + t + 1] = dur;
            d_dur[b] = dur;
        }
    }
    __syncthreads();

    float a0 = saw[0], a1 = saw[1], a2 = saw[2];
    size_t ab = O4 + ((size_t)t*Bc + b)*Dc;
    const float* S0 = S + (size_t)b*Dc;
    const float* S1 = S + ((size_t)Bc + b)*Dc;
    const float* S2 = S + ((size_t)2*Bc + b)*Dc;
    for (int d = th; d < Dc; d += 512)
        out[ab + d] = a0*S0[d] + a1*S1[d] + a2*S2[d];
}

// ---------------- host ------------------------------------------------------
extern "C" void kernel_launch(void* const* d_in, const int* in_sizes, int n_in,
                              void* d_out, int out_size)
{
    const float* S     = (const float*)d_in[0];
    const float* R     = (const float*)d_in[1];
    const float* cls_W = (const float*)d_in[2];
    const float* cls_b = (const float*)d_in[3];
    const float* dur_W = (const float*)d_in[4];
    const float* dur_b = (const float*)d_in[5];
    const float* lin_W = (const float*)d_in[6];
    const float* lin_b = (const float*)d_in[7];
    const float* W_ih  = (const float*)d_in[8];
    const float* W_hh  = (const float*)d_in[9];
    const float* b_ih  = (const float*)d_in[10];
    const float* b_hh  = (const float*)d_in[11];
    const float* Wp    = (const float*)d_in[12];
    const float* bp    = (const float*)d_in[13];
    const float* Wdur  = (const float*)d_in[14];
    const float* bdur  = (const float*)d_in[15];
    const float* embed = (const float*)d_in[16];
    const float* Wattn = (const float*)d_in[17];
    float* out = (float*)d_out;

    float *pfeat, *px0, *pxp, *pgx0, *pE, *pEp, *pP, *pgates, *ph, *pbsum;
    cudaGetSymbolAddress((void**)&pfeat,  d_feat);
    cudaGetSymbolAddress((void**)&px0,    d_x0);
    cudaGetSymbolAddress((void**)&pxp,    d_xp);
    cudaGetSymbolAddress((void**)&pgx0,   d_gx0);
    cudaGetSymbolAddress((void**)&pE,     d_E);
    cudaGetSymbolAddress((void**)&pEp,    d_Ep);
    cudaGetSymbolAddress((void**)&pP,     d_P);
    cudaGetSymbolAddress((void**)&pgates, d_gates);
    cudaGetSymbolAddress((void**)&ph,     d_h);
    cudaGetSymbolAddress((void**)&pbsum,  d_bsum);

    init_kernel<<<256, 512>>>(W_ih, b_ih, b_hh, Wp);

    cls_kernel<<<dim3(Bc/32, Kc), 256>>>(S, R, cls_W, cls_b);
    prep_kernel<<<Bc, 256>>>(S, R, dur_W, dur_b, Wdur, out);

    // x0 = feat @ lin_W + lin_b   [512 x 1025, K=6288]  split-K 2 (grid 144)
    gemm6<false><<<dim3(9, 8, 2), 256>>>(
        pfeat, lin_W, pxp, Bc, DP1, FEATN/2, FEATN, DP1, DP1, nullptr,
        (long long)(FEATN/2), (long long)(FEATN/2)*DP1, (long long)Bc*DP1);
    reduce_add<<<(Bc*DP1 + 255)/256, 256>>>(pxp, px0, Bc*DP1, 2,
                                            (long long)Bc*DP1, lin_b, DP1);
    // gx0 = x0 @ W_ih^T + bsum   [512 x 2048, K=1025]  (grid 128)
    gemm6<true><<<dim3(16, 8), 256>>>(
        px0, W_ih, pgx0, Bc, G4, DP1, DP1, DP1, G4, pbsum, 0, 0, 0);
    // E = embed @ W_ih[:, :D]^T  [48 x 2048, K=1024]  split-K 4 (grid 64)
    gemm6<true><<<dim3(16, 1, 4), 256>>>(
        embed, W_ih, pEp, Cc, G4, Dc/4, Dc, DP1, G4, nullptr,
        (long long)(Dc/4), (long long)(Dc/4), (long long)Cc*G4);
    reduce_add<<<(Cc*G4 + 255)/256, 256>>>(pEp, pE, Cc*G4, 4,
                                           (long long)Cc*G4, nullptr, G4);
    // P_k = S_k @ Wattn^T        [512 x 512, K=1024]  batched x3 (grid 96)
    gemm6<true><<<dim3(4, 8, 3), 256>>>(
        S, Wattn, pP, Bc, Hc, Dc, Dc, Dc, Hc, nullptr,
        (long long)Bc*Dc, 0, (long long)Bc*Hc);

    int sel = 0;
    for (int t = 0; t < Tc; t++) {
        if (t > 0)
            gemm6<true><<<dim3(16, 8), 256>>>(
                ph + (size_t)sel*Bc*Hc, W_hh, pgates,
                Bc, G4, Hc, Hc, Hc, G4, pbsum, 0, 0, 0);
        step_kernel<<<Bc, 512>>>(S, bp, Wdur, bdur, out, t, sel);
        sel ^= 1;
    }
}

// round 10
// speedup vs baseline: 1.3720x; 1.3139x over previous
#include <cuda_runtime.h>
#include <math.h>

#define Kc 3
#define Bc 512
#define Dc 1024
#define Hc 512
#define Cc 48
#define Tc 25
#define G4 2048
#define DP1 1025
#define FEATN 6288
#define FEATNP 6304          // FEATN padded to mult of 16
#define XP 1040              // DP1 padded to mult of 16
#define LWP 1152             // lin_W col pad (9 n-blocks * 128)

// output section offsets (all float32, concatenated in tuple order)
#define O0 0                                  // labels_t   [T,B]
#define O1 (Tc*Bc)                            // probs      [B,T,C]
#define O2 (O1 + Bc*Tc*Cc)                    // curr_action[B,C]
#define O3 (O2 + Bc*Cc)                       // durations  [B,T+1]
#define O4 (O3 + Bc*(Tc+1))                   // att_t      [T,B,D]

// ---------------- scratch (device globals: no allocation allowed) ----------
__device__ float d_Y[Kc*Bc*Cc];
__device__ float d_feat[Bc*FEATNP];
__device__ float d_x0p[Bc*XP];        // x0 padded [512][1040]
__device__ float d_xp[2*Bc*DP1];      // lin split-K partials
__device__ float d_gx0[Bc*G4];        // x0 @ W_ih^T + bsum
__device__ float d_E[Cc*G4];
__device__ float d_Ep[4*Cc*G4];
__device__ float d_P[Kc*Bc*Hc];
__device__ float d_sdur[Bc*Kc];
__device__ float d_gates[Bc*G4];
__device__ float d_h[2][Bc*Hc];
__device__ float d_c[Bc*Hc];
__device__ int   d_labels[Bc];
__device__ float d_dur[Bc];
__device__ float d_WpT[Cc*Hc];
__device__ float d_wihdur[G4];
__device__ float d_bsum[G4];
__device__ float d_Wihp[G4*XP];       // W_ih padded [2048][1040]
__device__ float d_linWp[FEATNP*LWP]; // lin_W padded [6304][1152]

// ---------------- tf32 helpers ----------------------------------------------
__device__ __forceinline__ void tsplit(float x, float &hf, float &lf) {
    unsigned h, l;
    asm("cvt.rna.tf32.f32 %0, %1;" : "=r"(h) : "f"(x));
    hf = __uint_as_float(h);
    float r = x - hf;
    asm("cvt.rna.tf32.f32 %0, %1;" : "=r"(l) : "f"(r));
    lf = __uint_as_float(l);
}
__device__ __forceinline__ void ldm4(unsigned* r, unsigned addr) {
    asm volatile("ldmatrix.sync.aligned.m8n8.x4.shared.b16 {%0,%1,%2,%3}, [%4];"
        : "=r"(r[0]), "=r"(r[1]), "=r"(r[2]), "=r"(r[3]) : "r"(addr));
}
__device__ __forceinline__ void mma8(float* c, const unsigned* a, const unsigned* b) {
    asm volatile("mma.sync.aligned.m16n8k8.row.col.f32.tf32.tf32.f32 "
        "{%0,%1,%2,%3},{%4,%5,%6,%7},{%8,%9},{%0,%1,%2,%3};"
        : "+f"(c[0]), "+f"(c[1]), "+f"(c[2]), "+f"(c[3])
        : "r"(a[0]), "r"(a[1]), "r"(a[2]), "r"(a[3]), "r"(b[0]), "r"(b[1]));
}
// swizzled word index of 16B chunk start (row stride 20 f32, 4 data chunks)
__device__ __forceinline__ int swz(int row, int chunk) {
    return row*20 + (((chunk ^ (row >> 3)) & 3) << 2);
}

// ---------------- tgemm: 64x128 tile, 3xTF32, NT/NN -------------------------
// C[m,n] = sum_k A[m,k]*B'[k,n] (+bias[n]).  256 threads, KSTEP=16.
// BT=true : B is [N,K] row-major;  BT=false: B is [K,N] row-major.
// K must be a multiple of 16 (pad arrays with zeros).  z batches/split-K.
template<bool BT>
__global__ void __launch_bounds__(256)
tgemm(const float* __restrict__ A, const float* __restrict__ Bm,
      float* __restrict__ C, int M, int N, int K,
      int lda, int ldb, int ldc, const float* __restrict__ bias,
      long long sA, long long sB, long long sC)
{
    __shared__ __align__(16) float As_hi[64*20], As_lo[64*20];
    __shared__ __align__(16) float Bs_hi[128*20], Bs_lo[128*20];

    A  += (size_t)blockIdx.z * sA;
    Bm += (size_t)blockIdx.z * sB;
    C  += (size_t)blockIdx.z * sC;

    const int tid  = threadIdx.x;
    const int lane = tid & 31, wid = tid >> 5;
    const int m0 = blockIdx.y * 64, n0 = blockIdx.x * 128;
    const int am = (wid & 1) * 32;        // warp m-base (2 warps in m)
    const int an = (wid >> 1) * 32;       // warp n-base (4 warps in n)

    const unsigned aH = (unsigned)__cvta_generic_to_shared(As_hi);
    const unsigned aL = (unsigned)__cvta_generic_to_shared(As_lo);
    const unsigned bH = (unsigned)__cvta_generic_to_shared(Bs_hi);
    const unsigned bL = (unsigned)__cvta_generic_to_shared(Bs_lo);

    float acc[2][4][4];
#pragma unroll
    for (int i = 0; i < 2; i++)
#pragma unroll
        for (int j = 0; j < 4; j++)
#pragma unroll
            for (int q = 0; q < 4; q++) acc[i][j][q] = 0.f;

    for (int k0 = 0; k0 < K; k0 += 16) {
        // -------- global loads into regs --------
        float4 va = make_float4(0.f, 0.f, 0.f, 0.f);
        {
            int row = tid >> 2, kq = tid & 3;
            if (m0 + row < M)
                va = *(const float4*)&A[(size_t)(m0+row)*lda + k0 + 4*kq];
        }
        float4 vb0 = make_float4(0.f,0.f,0.f,0.f), vb1 = vb0;
        if (BT) {
            int n = tid >> 1, h8 = (tid & 1) * 8;
            if (n0 + n < N) {
                const float* src = &Bm[(size_t)(n0+n)*ldb + k0 + h8];
                vb0 = *(const float4*)src;
                vb1 = *(const float4*)(src + 4);
            }
        } else {
            int k = tid >> 4, nq = tid & 15;
            const float* src = &Bm[(size_t)(k0+k)*ldb + n0 + 8*nq];
            vb0 = *(const float4*)src;
            vb1 = *(const float4*)(src + 4);
        }
        __syncthreads();
        // -------- split + smem stores --------
        {
            int row = tid >> 2, kq = tid & 3;
            float4 h4, l4;
            tsplit(va.x, h4.x, l4.x); tsplit(va.y, h4.y, l4.y);
            tsplit(va.z, h4.z, l4.z); tsplit(va.w, h4.w, l4.w);
            int w = swz(row, kq);
            *(float4*)&As_hi[w] = h4;
            *(float4*)&As_lo[w] = l4;
        }
        if (BT) {
            int n = tid >> 1, cb = (tid & 1) * 2;
            float4 h4, l4;
            tsplit(vb0.x, h4.x, l4.x); tsplit(vb0.y, h4.y, l4.y);
            tsplit(vb0.z, h4.z, l4.z); tsplit(vb0.w, h4.w, l4.w);
            int w = swz(n, cb);
            *(float4*)&Bs_hi[w] = h4; *(float4*)&Bs_lo[w] = l4;
            tsplit(vb1.x, h4.x, l4.x); tsplit(vb1.y, h4.y, l4.y);
            tsplit(vb1.z, h4.z, l4.z); tsplit(vb1.w, h4.w, l4.w);
            w = swz(n, cb + 1);
            *(float4*)&Bs_hi[w] = h4; *(float4*)&Bs_lo[w] = l4;
        } else {
            int k = tid >> 4, nq = tid & 15;
            const float* p0 = (const float*)&vb0;
            const float* p1 = (const float*)&vb1;
#pragma unroll
            for (int e = 0; e < 4; e++) {
                float hv, lv;
                int nl = 8*nq + e;
                int w = swz(nl, k >> 2) + (k & 3);
                tsplit(p0[e], hv, lv); Bs_hi[w] = hv; Bs_lo[w] = lv;
                nl += 4; w = swz(nl, k >> 2) + (k & 3);
                tsplit(p1[e], hv, lv); Bs_hi[w] = hv; Bs_lo[w] = lv;
            }
        }
        __syncthreads();
        // -------- compute: two k8 halves --------
#pragma unroll
        for (int half = 0; half < 2; half++) {
            const int kc = half * 8;
            unsigned ah[2][4], al[2][4], bh[4][2], bl[4][2];
#pragma unroll
            for (int i = 0; i < 2; i++) {
                int row = am + 16*i + (lane & 15);
                int chunk = (kc >> 2) + (lane >> 4);
                unsigned off = 4u * (unsigned)swz(row, chunk);
                ldm4(ah[i], aH + off);
                ldm4(al[i], aL + off);
            }
#pragma unroll
            for (int g = 0; g < 2; g++) {
                int row = an + 16*g + (lane & 7) + ((lane >> 4) << 3);
                int chunk = (kc >> 2) + ((lane >> 3) & 1);
                unsigned off = 4u * (unsigned)swz(row, chunk);
                unsigned r[4];
                ldm4(r, bH + off);
                bh[2*g][0] = r[0]; bh[2*g][1] = r[1];
                bh[2*g+1][0] = r[2]; bh[2*g+1][1] = r[3];
                ldm4(r, bL + off);
                bl[2*g][0] = r[0]; bl[2*g][1] = r[1];
                bl[2*g+1][0] = r[2]; bl[2*g+1][1] = r[3];
            }
#pragma unroll
            for (int i = 0; i < 2; i++)
#pragma unroll
                for (int j = 0; j < 4; j++) {
                    mma8(acc[i][j], ah[i], bh[j]);
                    mma8(acc[i][j], ah[i], bl[j]);
                    mma8(acc[i][j], al[i], bh[j]);
                }
        }
    }

    // -------- epilogue --------
#pragma unroll
    for (int i = 0; i < 2; i++) {
#pragma unroll
        for (int j = 0; j < 4; j++) {
            int r0 = m0 + am + 16*i + (lane >> 2);
            int c0 = n0 + an + 8*j + (lane & 3) * 2;
            float b0 = 0.f, b1 = 0.f;
            if (bias) {
                if (c0 < N)     b0 = bias[c0];
                if (c0 + 1 < N) b1 = bias[c0 + 1];
            }
            if (r0 < M) {
                if (c0 < N)     C[(size_t)r0*ldc + c0]     = acc[i][j][0] + b0;
                if (c0 + 1 < N) C[(size_t)r0*ldc + c0 + 1] = acc[i][j][1] + b1;
            }
            if (r0 + 8 < M) {
                if (c0 < N)     C[(size_t)(r0+8)*ldc + c0]     = acc[i][j][2] + b0;
                if (c0 + 1 < N) C[(size_t)(r0+8)*ldc + c0 + 1] = acc[i][j][3] + b1;
            }
        }
    }
}

// ---------------- pad copy ---------------------------------------------------
__global__ void pad_copy(const float* __restrict__ src, float* __restrict__ dst,
                         int srows, int scols, int drows, int dcols)
{
    for (long long i = blockIdx.x*(long long)blockDim.x + threadIdx.x;
         i < (long long)drows*dcols; i += (long long)gridDim.x*blockDim.x) {
        int r = (int)(i / dcols), c = (int)(i % dcols);
        dst[i] = (r < srows && c < scols) ? src[(size_t)r*scols + c] : 0.f;
    }
}

// ---------------- split-K reduce (E) + padded reduce (x0) -------------------
__global__ void reduce_add(const float* __restrict__ part, float* __restrict__ outp,
                           int n, int nparts, long long stride)
{
    int i = blockIdx.x * blockDim.x + threadIdx.x;
    if (i >= n) return;
    float s = 0.f;
    for (int z = 0; z < nparts; z++) s += part[(size_t)z*stride + i];
    outp[i] = s;
}

__global__ void reduce_x0(const float* __restrict__ lin_b)
{
    int i = blockIdx.x * blockDim.x + threadIdx.x;
    if (i >= Bc*XP) return;
    int row = i / XP, col = i % XP;
    float v = 0.f;
    if (col < DP1)
        v = d_xp[(size_t)row*DP1 + col] + d_xp[(size_t)Bc*DP1 + (size_t)row*DP1 + col]
          + lin_b[col];
    d_x0p[i] = v;
}

// ---------------- init ------------------------------------------------------
__global__ void init_kernel(const float* __restrict__ W_ih,
                            const float* __restrict__ b_ih,
                            const float* __restrict__ b_hh,
                            const float* __restrict__ Wp)
{
    for (int i = blockIdx.x*blockDim.x + threadIdx.x; i < Bc*Hc;
         i += gridDim.x*blockDim.x) {
        d_h[0][i] = 0.f; d_c[i] = 0.f;
        if (i < Cc*Hc) {
            int c = i >> 9, h = i & 511;
            d_WpT[i] = Wp[h*Cc + c];
        }
        if (i < G4) {
            d_wihdur[i] = W_ih[(size_t)i*DP1 + Dc];
            d_bsum[i]   = b_ih[i] + b_hh[i];
        }
    }
}

// ---------------- fused classifier: logits + softmax ------------------------
__global__ void __launch_bounds__(256)
cls_kernel(const float* __restrict__ S, const float* __restrict__ R,
           const float* __restrict__ W, const float* __restrict__ bcls)
{
    __shared__ __align__(16) float As[32][20];
    __shared__ __align__(16) float Bs[48][20];
    const int k  = blockIdx.y;
    const int b0 = blockIdx.x * 32;
    const int tid = threadIdx.x;
    const int rr = tid >> 3, cs = tid & 7;
    float acc[6] = {};

    for (int ph = 0; ph < 2; ph++) {
        const float* Ap = (ph ? R : S) + ((size_t)k*Bc + b0)*Dc;
        const float* Wb = W + ((size_t)k*2*Dc + (size_t)ph*Dc)*Cc;
        for (int k0 = 0; k0 < Dc; k0 += 16) {
            {   int lk = tid & 15, lr = tid >> 4;
                As[lr][lk]      = Ap[(size_t)lr*Dc + k0 + lk];
                As[lr + 16][lk] = Ap[(size_t)(lr + 16)*Dc + k0 + lk];
            }
#pragma unroll
            for (int j = 0; j < 3; j++) {
                int idx = tid + j*256;
                int c = idx >> 4, kk = idx & 15;
                Bs[c][kk] = Wb[(size_t)(k0 + kk)*Cc + c];
            }
            __syncthreads();
#pragma unroll
            for (int kq = 0; kq < 4; kq++) {
                float4 a = *reinterpret_cast<const float4*>(&As[rr][kq*4]);
#pragma unroll
                for (int j = 0; j < 6; j++) {
                    float4 b = *reinterpret_cast<const float4*>(&Bs[cs + 8*j][kq*4]);
                    acc[j] = fmaf(a.x, b.x, acc[j]);
                    acc[j] = fmaf(a.y, b.y, acc[j]);
                    acc[j] = fmaf(a.z, b.z, acc[j]);
                    acc[j] = fmaf(a.w, b.w, acc[j]);
                }
            }
            __syncthreads();
        }
    }
    float mx = -3.4e38f;
#pragma unroll
    for (int j = 0; j < 6; j++) {
        acc[j] += bcls[k*Cc + cs + 8*j];
        mx = fmaxf(mx, acc[j]);
    }
    for (int o = 4; o; o >>= 1) mx = fmaxf(mx, __shfl_xor_sync(0xffffffffu, mx, o));
    float sum = 0.f;
#pragma unroll
    for (int j = 0; j < 6; j++) { acc[j] = expf(acc[j] - mx); sum += acc[j]; }
    for (int o = 4; o; o >>= 1) sum += __shfl_xor_sync(0xffffffffu, sum, o);
    float inv = 1.f / sum;
    float* Yr = d_Y + ((size_t)k*Bc + b0 + rr)*Cc;
#pragma unroll
    for (int j = 0; j < 6; j++) Yr[cs + 8*j] = acc[j] * inv;
}

// feat assembly + curr_action + curr_dur + sdur ; one block per b
__global__ void prep_kernel(const float* __restrict__ S, const float* __restrict__ R,
                            const float* __restrict__ dur_W, const float* __restrict__ dur_b,
                            const float* __restrict__ Wdur, float* __restrict__ out)
{
    __shared__ float red[256];
    const int b = blockIdx.x, tid = threadIdx.x;
    float* fr = d_feat + (size_t)b * FEATNP;
    for (int i = tid; i < Kc*Cc; i += 256) {
        int k = i / Cc, c = i - k*Cc;
        fr[i] = d_Y[((size_t)k*Bc + b)*Cc + c];
    }
    for (int i = tid; i < Kc*Dc; i += 256) {
        int k = i >> 10, d = i & 1023;
        fr[Kc*Cc + i]         = S[((size_t)k*Bc + b)*Dc + d];
        fr[Kc*Cc + Kc*Dc + i] = R[((size_t)k*Bc + b)*Dc + d];
    }
    if (tid < FEATNP - FEATN) fr[FEATN + tid] = 0.f;   // zero pad cols
    for (int i = tid; i < Cc; i += 256)
        out[O2 + (size_t)b*Cc + i] = d_Y[(size_t)b*Cc + i]
                                   + d_Y[((size_t)Bc + b)*Cc + i]
                                   + d_Y[((size_t)2*Bc + b)*Cc + i];
    float pd = 0.f;
    for (int i = tid; i < Kc*Dc; i += 256) {
        int k = i >> 10, d = i & 1023;
        pd += R[((size_t)k*Bc + b)*Dc + d] * dur_W[i];
    }
    red[tid] = pd; __syncthreads();
    for (int s = 128; s > 0; s >>= 1) { if (tid < s) red[tid] += red[tid + s]; __syncthreads(); }
    if (tid == 0) out[O3 + (size_t)b*(Tc+1)] = red[0] + dur_b[0];
    __syncthreads();
    for (int k = 0; k < Kc; k++) {
        float ps = 0.f;
        for (int d = tid; d < Dc; d += 256)
            ps += S[((size_t)k*Bc + b)*Dc + d] * Wdur[d];
        red[tid] = ps; __syncthreads();
        for (int s = 128; s > 0; s >>= 1) { if (tid < s) red[tid] += red[tid + s]; __syncthreads(); }
        if (tid == 0) d_sdur[b*Kc + k] = red[0];
        __syncthreads();
    }
}

// fused per-step kernel: LSTM elementwise + logits/probs/argmax + attention +
// dur ; one block per b, 512 threads (16 warps). bsum already folded in GEMMs.
__global__ void __launch_bounds__(512)
step_kernel(const float* __restrict__ S, const float* __restrict__ bp,
            const float* __restrict__ Wdur, const float* __restrict__ bdur,
            float* __restrict__ out, int t, int sel)
{
    __shared__ float sh[Hc];
    __shared__ float slog[Cc];
    __shared__ float sscore[3];
    __shared__ float saw[3];
    __shared__ float sred[16];
    const int b  = blockIdx.x;
    const int th = threadIdx.x;
    const int wid = th >> 5, lane = th & 31;
    const float* h_in = d_h[sel];
    float* h_out = d_h[sel ^ 1];

    float g[4];
    if (t == 0) {
#pragma unroll
        for (int j = 0; j < 4; j++) g[j] = d_gx0[(size_t)b*G4 + j*Hc + th];
    } else {
        int lab = d_labels[b];
        float dp = d_dur[b];
#pragma unroll
        for (int j = 0; j < 4; j++) {
            int gi = j*Hc + th;
            g[j] = d_gates[(size_t)b*G4 + gi] + d_E[(size_t)lab*G4 + gi]
                 + dp * d_wihdur[gi];
        }
    }
    float ig = 1.f / (1.f + expf(-g[0]));
    float fg = 1.f / (1.f + expf(-g[1]));
    float gg = tanhf(g[2]);
    float og = 1.f / (1.f + expf(-g[3]));
    int idx = b*Hc + th;
    float cn = fg * d_c[idx] + ig * gg;
    d_c[idx] = cn;
    float hn = og * tanhf(cn);
    h_out[idx] = hn;
    sh[th] = hn;
    float hp = h_in[idx] * Wdur[Dc + th];
    for (int o = 16; o; o >>= 1) hp += __shfl_xor_sync(0xffffffffu, hp, o);
    if (lane == 0) sred[wid] = hp;
    __syncthreads();

    for (int cc = wid; cc < Cc; cc += 16) {
        float s = 0.f;
        const float* wr = d_WpT + (size_t)cc*Hc;
        for (int j = lane; j < Hc; j += 32) s += sh[j] * wr[j];
        for (int o = 16; o; o >>= 1) s += __shfl_xor_sync(0xffffffffu, s, o);
        if (lane == 0) slog[cc] = s + bp[cc];
    }
    if (wid < 3) {
        float s = 0.f;
        const float* Pr = d_P + ((size_t)wid*Bc + b)*Hc;
        for (int j = lane; j < Hc; j += 32) s += sh[j] * Pr[j];
        for (int o = 16; o; o >>= 1) s += __shfl_xor_sync(0xffffffffu, s, o);
        if (lane == 0) sscore[wid] = s * 0.03125f;  // 1/sqrt(1024)
    }
    __syncthreads();

    if (wid == 0) {
        float v1 = slog[lane];
        float v2 = (lane < Cc - 32) ? slog[32 + lane] : -3.4e38f;
        float m = fmaxf(v1, v2);
        for (int o = 16; o; o >>= 1) m = fmaxf(m, __shfl_xor_sync(0xffffffffu, m, o));
        float e1 = expf(v1 - m);
        float e2 = (lane < Cc - 32) ? expf(v2 - m) : 0.f;
        float s = e1 + e2;
        for (int o = 16; o; o >>= 1) s += __shfl_xor_sync(0xffffffffu, s, o);
        float inv = 1.f / s;
        size_t pb = O1 + ((size_t)b*Tc + t)*Cc;
        out[pb + lane] = e1 * inv;
        if (lane < Cc - 32) out[pb + 32 + lane] = e2 * inv;
        float bv; int bi;
        if (lane < Cc - 32 && v2 > v1) { bv = v2; bi = 32 + lane; }
        else                           { bv = v1; bi = lane; }
        for (int o = 16; o; o >>= 1) {
            float ov = __shfl_xor_sync(0xffffffffu, bv, o);
            int   oi = __shfl_xor_sync(0xffffffffu, bi, o);
            if (ov > bv || (ov == bv && oi < bi)) { bv = ov; bi = oi; }
        }
        float hv = (lane < 16) ? sred[lane] : 0.f;
        for (int o = 8; o; o >>= 1) hv += __shfl_xor_sync(0xffffffffu, hv, o);
        if (lane == 0) {
            out[O0 + (size_t)t*Bc + b] = (float)bi;
            d_labels[b] = bi;
            float s0 = sscore[0], s1 = sscore[1], s2 = sscore[2];
            float sm = fmaxf(s0, fmaxf(s1, s2));
            float a0 = expf(s0 - sm), a1 = expf(s1 - sm), a2 = expf(s2 - sm);
            float z = 1.f / (a0 + a1 + a2);
            a0 *= z; a1 *= z; a2 *= z;
            saw[0] = a0; saw[1] = a1; saw[2] = a2;
            float dur = a0*d_sdur[b*Kc] + a1*d_sdur[b*Kc+1] + a2*d_sdur[b*Kc+2]
                      + hv + bdur[0];
            out[O3 + (size_t)b*(Tc+1) + t + 1] = dur;
            d_dur[b] = dur;
        }
    }
    __syncthreads();

    float a0 = saw[0], a1 = saw[1], a2 = saw[2];
    size_t ab = O4 + ((size_t)t*Bc + b)*Dc;
    const float* S0 = S + (size_t)b*Dc;
    const float* S1 = S + ((size_t)Bc + b)*Dc;
    const float* S2 = S + ((size_t)2*Bc + b)*Dc;
    for (int d = th; d < Dc; d += 512)
        out[ab + d] = a0*S0[d] + a1*S1[d] + a2*S2[d];
}

// ---------------- host ------------------------------------------------------
extern "C" void kernel_launch(void* const* d_in, const int* in_sizes, int n_in,
                              void* d_out, int out_size)
{
    const float* S     = (const float*)d_in[0];
    const float* R     = (const float*)d_in[1];
    const float* cls_W = (const float*)d_in[2];
    const float* cls_b = (const float*)d_in[3];
    const float* dur_W = (const float*)d_in[4];
    const float* dur_b = (const float*)d_in[5];
    const float* lin_W = (const float*)d_in[6];
    const float* lin_b = (const float*)d_in[7];
    const float* W_ih  = (const float*)d_in[8];
    const float* W_hh  = (const float*)d_in[9];
    const float* b_ih  = (const float*)d_in[10];
    const float* b_hh  = (const float*)d_in[11];
    const float* Wp    = (const float*)d_in[12];
    const float* bp    = (const float*)d_in[13];
    const float* Wdur  = (const float*)d_in[14];
    const float* bdur  = (const float*)d_in[15];
    const float* embed = (const float*)d_in[16];
    const float* Wattn = (const float*)d_in[17];
    float* out = (float*)d_out;

    float *pfeat, *px0p, *pxp, *pgx0, *pE, *pEp, *pP, *pgates, *ph, *pbsum;
    float *pWihp, *plinWp;
    cudaGetSymbolAddress((void**)&pfeat,  d_feat);
    cudaGetSymbolAddress((void**)&px0p,   d_x0p);
    cudaGetSymbolAddress((void**)&pxp,    d_xp);
    cudaGetSymbolAddress((void**)&pgx0,   d_gx0);
    cudaGetSymbolAddress((void**)&pE,     d_E);
    cudaGetSymbolAddress((void**)&pEp,    d_Ep);
    cudaGetSymbolAddress((void**)&pP,     d_P);
    cudaGetSymbolAddress((void**)&pgates, d_gates);
    cudaGetSymbolAddress((void**)&ph,     d_h);
    cudaGetSymbolAddress((void**)&pbsum,  d_bsum);
    cudaGetSymbolAddress((void**)&pWihp,  d_Wihp);
    cudaGetSymbolAddress((void**)&plinWp, d_linWp);

    init_kernel<<<256, 512>>>(W_ih, b_ih, b_hh, Wp);
    // padded weight copies (zero-filled pads make K-mult-16 loops exact)
    pad_copy<<<512, 256>>>(W_ih,  pWihp,  G4,    DP1, G4,     XP);
    pad_copy<<<1024, 256>>>(lin_W, plinWp, FEATN, DP1, FEATNP, LWP);

    cls_kernel<<<dim3(Bc/32, Kc), 256>>>(S, R, cls_W, cls_b);
    prep_kernel<<<Bc, 256>>>(S, R, dur_W, dur_b, Wdur, out);

    // x0 = feat @ lin_W + lin_b  [512 x 1025, K=6304]  split-K 2 (144 blocks)
    tgemm<false><<<dim3(9, 8, 2), 256>>>(
        pfeat, plinWp, pxp, Bc, DP1, FEATNP/2, FEATNP, LWP, DP1, nullptr,
        (long long)(FEATNP/2), (long long)(FEATNP/2)*LWP, (long long)Bc*DP1);
    reduce_x0<<<(Bc*XP + 255)/256, 256>>>(lin_b);
    // gx0 = x0 @ W_ih^T + bsum  [512 x 2048, K=1040]  (128 blocks)
    tgemm<true><<<dim3(16, 8), 256>>>(
        px0p, pWihp, pgx0, Bc, G4, XP, XP, XP, G4, pbsum, 0, 0, 0);
    // E = embed @ W_ih[:, :D]^T  [48 x 2048, K=1024]  split-K 4 (64 blocks)
    tgemm<true><<<dim3(16, 1, 4), 256>>>(
        embed, pWihp, pEp, Cc, G4, Dc/4, Dc, XP, G4, nullptr,
        (long long)(Dc/4), (long long)(Dc/4), (long long)Cc*G4);
    reduce_add<<<(Cc*G4 + 255)/256, 256>>>(pEp, pE, Cc*G4, 4, (long long)Cc*G4);
    // P = S_flat @ Wattn^T  [1536 x 512, K=1024]  (96 blocks)
    tgemm<true><<<dim3(4, 24), 256>>>(
        S, Wattn, pP, Kc*Bc, Hc, Dc, Dc, Dc, Hc, nullptr, 0, 0, 0);

    int sel = 0;
    for (int t = 0; t < Tc; t++) {
        if (t > 0)
            tgemm<true><<<dim3(16, 8), 256>>>(
                ph + (size_t)sel*Bc*Hc, W_hh, pgates,
                Bc, G4, Hc, Hc, Hc, G4, pbsum, 0, 0, 0);
        step_kernel<<<Bc, 512>>>(S, bp, Wdur, bdur, out, t, sel);
        sel ^= 1;
    }
}